// round 9
// baseline (speedup 1.0000x reference)
#include <cuda_runtime.h>
#include <math.h>
#include <stdint.h>

#define B 256
#define T 512
#define F 128
#define H 256
#define H3 768
#define BH (B * H)

// Static device scratch for the hoisted input projection: MX[t*B+b][0..767]
__device__ float g_mx[(size_t)T * B * H3];   // ~402 MB

// Flags: [batch-group][sub*8 + j-tile], one 128B line per flag
#define NJB 8
#define NBB 16
__device__ unsigned g_flags[NBB][16 * 32];

// ---------------------------------------------------------------------------
// Helpers
// ---------------------------------------------------------------------------
__device__ __forceinline__ void ffma2(unsigned long long &acc,
                                      unsigned long long a,
                                      unsigned long long b) {
    asm("fma.rn.f32x2 %0, %1, %2, %0;" : "+l"(acc) : "l"(a), "l"(b));
}
__device__ __forceinline__ unsigned long long dup2(float v) {
    unsigned long long r;
    asm("mov.b64 %0, {%1, %1};" : "=l"(r) : "f"(v));
    return r;
}
__device__ __forceinline__ float2 unpk(unsigned long long v) {
    float2 r;
    asm("mov.b64 {%0, %1}, %2;" : "=f"(r.x), "=f"(r.y) : "l"(v));
    return r;
}
__device__ __forceinline__ float tanh_fast(float x) {
    float y;
    asm("tanh.approx.f32 %0, %1;" : "=f"(y) : "f"(x));
    return y;
}
__device__ __forceinline__ float sig_fast(float x) {
    return fmaf(0.5f, tanh_fast(0.5f * x), 0.5f);
}
__device__ __forceinline__ unsigned ld_acq(const unsigned* p) {
    unsigned v;
    asm volatile("ld.acquire.gpu.global.u32 %0, [%1];" : "=r"(v) : "l"(p));
    return v;
}
__device__ __forceinline__ void st_rel(unsigned* p, unsigned v) {
    asm volatile("st.release.gpu.global.u32 [%0], %1;" :: "l"(p), "r"(v) : "memory");
}
__device__ __forceinline__ void bar_compute() {
    asm volatile("bar.sync 1, 512;" ::: "memory");
}

// ---------------------------------------------------------------------------
// Kernel 1: MX[m, n] = x[b, t, :] @ W[:, n] + bias_in[n],  m = t*B + b
// ---------------------------------------------------------------------------
#define GM_BM 64
#define GM_BN 64
#define GM_BK 32

__global__ __launch_bounds__(256) void mx_gemm(const float* __restrict__ x,
                                               const float* __restrict__ w,
                                               const float* __restrict__ bias) {
    __shared__ float As[GM_BK][GM_BM + 4];
    __shared__ float Bs[GM_BK][GM_BN];

    const int bm = blockIdx.y * GM_BM;
    const int bn = blockIdx.x * GM_BN;
    const int tid = (int)threadIdx.x;
    const int tm = (tid >> 4) << 2;
    const int tn = (tid & 15) << 2;

    unsigned long long acc2[4][2];
    #pragma unroll
    for (int i = 0; i < 4; i++) { acc2[i][0] = 0ull; acc2[i][1] = 0ull; }

    for (int k0 = 0; k0 < F; k0 += GM_BK) {
        #pragma unroll
        for (int i = 0; i < 2; i++) {
            int idx = tid + i * 256;
            int r = idx >> 3;
            int c = (idx & 7) << 2;
            int m = bm + r;
            int t = m >> 8;
            int b = m & 255;
            float4 v = *(const float4*)&x[((size_t)b * T + t) * F + k0 + c];
            As[c + 0][r] = v.x;
            As[c + 1][r] = v.y;
            As[c + 2][r] = v.z;
            As[c + 3][r] = v.w;
        }
        #pragma unroll
        for (int i = 0; i < 2; i++) {
            int idx = tid + i * 256;
            int r = idx >> 4;
            int c = (idx & 15) << 2;
            *(float4*)&Bs[r][c] = *(const float4*)&w[(size_t)(k0 + r) * H3 + bn + c];
        }
        __syncthreads();

        #pragma unroll
        for (int k = 0; k < GM_BK; k++) {
            unsigned long long a0 = dup2(As[k][tm + 0]);
            unsigned long long a1 = dup2(As[k][tm + 1]);
            unsigned long long a2 = dup2(As[k][tm + 2]);
            unsigned long long a3 = dup2(As[k][tm + 3]);
            const unsigned long long* bsk = (const unsigned long long*)&Bs[k][tn];
            unsigned long long b01 = bsk[0];
            unsigned long long b23 = bsk[1];
            ffma2(acc2[0][0], a0, b01); ffma2(acc2[0][1], a0, b23);
            ffma2(acc2[1][0], a1, b01); ffma2(acc2[1][1], a1, b23);
            ffma2(acc2[2][0], a2, b01); ffma2(acc2[2][1], a2, b23);
            ffma2(acc2[3][0], a3, b01); ffma2(acc2[3][1], a3, b23);
        }
        __syncthreads();
    }

    float4 bz4 = *(const float4*)&bias[bn + tn];
    #pragma unroll
    for (int i = 0; i < 4; i++) {
        float2 lo = unpk(acc2[i][0]);
        float2 hi = unpk(acc2[i][1]);
        float4 o;
        o.x = lo.x + bz4.x;
        o.y = lo.y + bz4.y;
        o.z = hi.x + bz4.z;
        o.w = hi.y + bz4.w;
        *(float4*)&g_mx[(size_t)(bm + tm + i) * H3 + bn + tn] = o;
    }
}

// ---------------------------------------------------------------------------
// Kernel 2: persistent GRU recurrence, half-step pipelined version.
// Grid (8 j-tiles, 16 b-groups) = 128 blocks, 576 threads
// (16 compute warps + 2 stager warps), 1 block/SM.
// The 16 batch rows split into subA (0-7) / subB (8-15), separate flags.
// Iteration t: computeA -> publish flagA -> computeB -> publish flagB.
// Stager warp s stages peer sub-s tiles (poll flag, LDG, STS, bump smem
// counter) concurrently with compute; consumers wait on smem counters only.
// Own j-tile h goes register->STS in phase C (never via L2).
// ---------------------------------------------------------------------------
#define BT 16
#define JT 32
#define WS_FLOATS (256 * 96)
#define HSS 264                      // h row stride (16B aligned, bank-skewed)
#define SUB_HS (8 * HSS)             // one sub, one buffer
#define HS_FLOATS (4 * SUB_HS)       // [sub][buf]
#define PT_FLOATS (8 * 8 * 96)       // [kg][row][96]
#define SMEM_BYTES ((WS_FLOATS + HS_FLOATS + PT_FLOATS) * 4 + 128)

extern __shared__ float smem_dyn[];

__global__ __launch_bounds__(576, 1)
void gru_persist(const float* __restrict__ mx,
                 const float* __restrict__ wr,
                 const float* __restrict__ rbias,
                 float* __restrict__ out) {
    float* ws = smem_dyn;                          // [k=256][96]
    float* hs = ws + WS_FLOATS;                    // [sub][buf][8][HSS]
    float* pt = hs + HS_FLOATS;                    // [kg=8][8][96]
    unsigned* cnt = (unsigned*)(pt + PT_FLOATS);   // [sub*8 + kg]

    const int tid = (int)threadIdx.x;              // 0..575
    const int wid = tid >> 5;                      // 0..17
    const int lane = tid & 31;
    const int jb = (int)blockIdx.x;                // 0..7
    const int ib = (int)blockIdx.y;                // 0..15
    const int b0 = ib * BT;
    const int j0 = jb * JT;

    // Load Wr slice once (all 576 threads)
    for (int idx = tid; idx < WS_FLOATS / 2; idx += 576) {
        int k = idx / 48;
        int c2 = idx % 48;
        int g = c2 >> 4;
        int jj = (c2 & 15) << 1;
        float2 v = *(const float2*)&wr[(size_t)k * H3 + g * H + j0 + jj];
        *(float2*)&ws[k * 96 + g * 32 + jj] = v;
    }
    if (tid < 16) cnt[tid] = 0u;
    // zero h buffers (hygiene)
    for (int i = tid; i < HS_FLOATS; i += 576) hs[i] = 0.0f;
    __syncthreads();

    if (wid < 16) {
        // ================= COMPUTE WARPS (512 threads) =================
        // Phase-A mapping: kg 0..7 (32 k's), 64 threads: 8 rows x 8 j-quads
        const int kg = tid >> 6;                   // 0..7
        const int r6 = tid & 63;
        const int rloc = r6 >> 3;                  // 0..7 (row within sub)
        const int jqa = (r6 & 7) << 2;             // 0,4,...,28

        // Phase-C mapping: one element; tid<256 -> subA rows 0-7, else subB
        const int bcE = tid >> 5;                  // 0..15
        const int er = bcE & 7;                    // row within sub
        const int jc = tid & 31;
        const int mysub = (tid < 256) ? 0 : 1;

        const float bz = rbias[j0 + jc];
        const float br = rbias[H + j0 + jc];
        const float bh = rbias[2 * H + j0 + jc];

        float hp = 0.0f;                           // carried own h element

        for (int t = 0; t < T; t++) {
            // prefetch mx gate inputs for this thread's element
            const float* mxr = mx + ((size_t)t * B + (b0 + bcE)) * H3 + (j0 + jc);
            float xz = mxr[0];
            float xr = mxr[H];
            float xh = mxr[2 * H];

            const int rbuf = (t - 1) & 1;          // read buffer (h(t-1))
            const int wbuf = t & 1;                // write buffer (h(t))

            #pragma unroll
            for (int s = 0; s < 2; s++) {
                // ---- phase A: partial mh for sub s over this kg's 32 k's ----
                unsigned long long az0 = 0, az1 = 0, ar0 = 0, ar1 = 0,
                                   ah0 = 0, ah1 = 0;
                if (t > 0) {
                    if (kg != jb) {
                        volatile unsigned* cp = &cnt[s * 8 + kg];
                        while (*cp < (unsigned)t) { __nanosleep(16); }
                        __threadfence_block();
                    }
                    const float* hrow = hs + (s * 2 + rbuf) * SUB_HS + rloc * HSS;
                    const int k_beg = kg * 32;
                    #pragma unroll
                    for (int kk = 0; kk < 32; kk += 4) {
                        float4 h4 = *(const float4*)&hrow[k_beg + kk];
                        float hv[4] = {h4.x, h4.y, h4.z, h4.w};
                        #pragma unroll
                        for (int u = 0; u < 4; u++) {
                            const float* wk = ws + (size_t)(k_beg + kk + u) * 96 + jqa;
                            ulonglong2 wz = *(const ulonglong2*)(wk);
                            ulonglong2 wv = *(const ulonglong2*)(wk + 32);
                            ulonglong2 wh = *(const ulonglong2*)(wk + 64);
                            unsigned long long hd = dup2(hv[u]);
                            ffma2(az0, hd, wz.x); ffma2(az1, hd, wz.y);
                            ffma2(ar0, hd, wv.x); ffma2(ar1, hd, wv.y);
                            ffma2(ah0, hd, wh.x); ffma2(ah1, hd, wh.y);
                        }
                    }
                }
                // store partials
                {
                    float* pr = pt + (kg * 8 + rloc) * 96 + jqa;
                    ulonglong2 v;
                    v.x = az0; v.y = az1; *(ulonglong2*)(pr) = v;
                    v.x = ar0; v.y = ar1; *(ulonglong2*)(pr + 32) = v;
                    v.x = ah0; v.y = ah1; *(ulonglong2*)(pr + 64) = v;
                }
                bar_compute();

                // ---- phase C: this sub's owners reduce + gates + output ----
                if (mysub == s) {
                    float mz = 0.f, mr = 0.f, mh = 0.f;
                    #pragma unroll
                    for (int g2 = 0; g2 < 8; g2++) {
                        const float* p = pt + (g2 * 8 + er) * 96 + jc;
                        mz += p[0];
                        mr += p[32];
                        mh += p[64];
                    }
                    float z = sig_fast(xz + mz + bz);
                    float r = sig_fast(xr + mr + br);
                    float c = tanh_fast(xh + r * (mh + bh));
                    float o = c + z * (hp - c);
                    out[(size_t)t * BH + (size_t)(b0 + bcE) * H + j0 + jc] = o;
                    // own j-tile straight into next read buffer (no L2)
                    hs[(s * 2 + wbuf) * SUB_HS + er * HSS + j0 + jc] = o;
                    hp = o;
                }
                bar_compute();
                if (tid == 0) {
                    st_rel(&g_flags[ib][(s * 8 + jb) * 32], (unsigned)(t + 1));
                }
            }
        }
    } else {
        // ================= STAGER WARPS (warps 16, 17) =================
        const int s = wid - 16;                    // sub handled by this warp
        const int srow = lane >> 2;                // 0..7
        const int sc4 = (lane & 3) * 4;            // 0,4,8,12

        for (int tt = 1; tt < T; tt++) {
            const int buf = (tt - 1) & 1;
            float* hsb = hs + (s * 2 + buf) * SUB_HS;
            const float* hsrc = out + (size_t)(tt - 1) * BH
                              + (size_t)(b0 + s * 8 + srow) * H;
            #pragma unroll 1
            for (int pi = 1; pi < 8; pi++) {
                const int peer = (jb + pi) & 7;
                if (lane == 0) {
                    const unsigned* fp = &g_flags[ib][(s * 8 + peer) * 32];
                    while (ld_acq(fp) < (unsigned)tt) { __nanosleep(20); }
                }
                __syncwarp();
                const float* hrow = hsrc + peer * 32;
                float4 v0 = *(const float4*)&hrow[sc4];
                float4 v1 = *(const float4*)&hrow[sc4 + 16];
                float* hd = hsb + srow * HSS + peer * 32;
                *(float4*)&hd[sc4] = v0;
                *(float4*)&hd[sc4 + 16] = v1;
                __syncwarp();
                if (lane == 0) {
                    __threadfence_block();
                    atomicAdd(&cnt[s * 8 + peer], 1u);
                }
            }
        }
    }
}

// ---------------------------------------------------------------------------
// Launch
// ---------------------------------------------------------------------------
extern "C" void kernel_launch(void* const* d_in, const int* in_sizes, int n_in,
                              void* d_out, int out_size) {
    (void)in_sizes; (void)n_in; (void)out_size;
    const float* x    = (const float*)d_in[0];   // (B, T, F)
    const float* w    = (const float*)d_in[1];   // (F, 3H)
    const float* wr   = (const float*)d_in[2];   // (H, 3H)
    const float* bias = (const float*)d_in[3];   // (2, 3H)
    float* out = (float*)d_out;                  // (T, B, H)

    static int attr_set = 0;
    if (!attr_set) {
        cudaFuncSetAttribute(gru_persist,
                             cudaFuncAttributeMaxDynamicSharedMemorySize,
                             SMEM_BYTES);
        attr_set = 1;
    }

    float* mx;
    cudaGetSymbolAddress((void**)&mx, g_mx);
    void* flags;
    cudaGetSymbolAddress(&flags, g_flags);

    cudaMemsetAsync(flags, 0, sizeof(unsigned) * NBB * 16 * 32, 0);

    dim3 g1(H3 / GM_BN, (T * B) / GM_BM);        // (12, 2048)
    mx_gemm<<<g1, 256>>>(x, w, bias);

    const float* rbias = bias + H3;
    dim3 g2(NJB, NBB);                           // (8, 16) = 128 blocks
    gru_persist<<<g2, 576, SMEM_BYTES>>>(mx, wr, rbias, out);
}

// round 10
// speedup vs baseline: 2.8253x; 2.8253x over previous
#include <cuda_runtime.h>
#include <math.h>
#include <stdint.h>

#define B 256
#define T 512
#define F 128
#define H 256
#define H3 768
#define BH (B * H)

// Static device scratch for the hoisted input projection: MX[t*B+b][0..767]
__device__ float g_mx[(size_t)T * B * H3];   // ~402 MB

// Flag array for inter-block sync (one 128B line per flag)
#define NJB 8
#define NBB 16
__device__ unsigned g_flags[NBB][NJB * 32];

// ---------------------------------------------------------------------------
// Helpers
// ---------------------------------------------------------------------------
__device__ __forceinline__ void ffma2(unsigned long long &acc,
                                      unsigned long long a,
                                      unsigned long long b) {
    asm("fma.rn.f32x2 %0, %1, %2, %0;" : "+l"(acc) : "l"(a), "l"(b));
}
__device__ __forceinline__ unsigned long long dup2(float v) {
    unsigned long long r;
    asm("mov.b64 %0, {%1, %1};" : "=l"(r) : "f"(v));
    return r;
}
__device__ __forceinline__ float2 unpk(unsigned long long v) {
    float2 r;
    asm("mov.b64 {%0, %1}, %2;" : "=f"(r.x), "=f"(r.y) : "l"(v));
    return r;
}
__device__ __forceinline__ float tanh_fast(float x) {
    float y;
    asm("tanh.approx.f32 %0, %1;" : "=f"(y) : "f"(x));
    return y;
}
__device__ __forceinline__ float sig_fast(float x) {
    return fmaf(0.5f, tanh_fast(0.5f * x), 0.5f);
}
__device__ __forceinline__ unsigned ld_acq(const unsigned* p) {
    unsigned v;
    asm volatile("ld.acquire.gpu.global.u32 %0, [%1];" : "=r"(v) : "l"(p));
    return v;
}
__device__ __forceinline__ void st_rel(unsigned* p, unsigned v) {
    asm volatile("st.release.gpu.global.u32 [%0], %1;" :: "l"(p), "r"(v) : "memory");
}
__device__ __forceinline__ uint32_t f2tf(float x) {
    uint32_t r;
    asm("cvt.rna.tf32.f32 %0, %1;" : "=r"(r) : "f"(x));
    return r;
}
__device__ __forceinline__ void mma_tf32(float& d0, float& d1, float& d2, float& d3,
                                         uint32_t a0, uint32_t a1, uint32_t a2, uint32_t a3,
                                         uint32_t b0, uint32_t b1) {
    asm volatile(
        "mma.sync.aligned.m16n8k8.row.col.f32.tf32.tf32.f32 "
        "{%0,%1,%2,%3}, {%4,%5,%6,%7}, {%8,%9}, {%0,%1,%2,%3};"
        : "+f"(d0), "+f"(d1), "+f"(d2), "+f"(d3)
        : "r"(a0), "r"(a1), "r"(a2), "r"(a3), "r"(b0), "r"(b1));
}

// ---------------------------------------------------------------------------
// Kernel 1: MX[m, n] = x[b, t, :] @ W[:, n] + bias_in[n],  m = t*B + b
// ---------------------------------------------------------------------------
#define GM_BM 64
#define GM_BN 64
#define GM_BK 32

__global__ __launch_bounds__(256) void mx_gemm(const float* __restrict__ x,
                                               const float* __restrict__ w,
                                               const float* __restrict__ bias) {
    __shared__ float As[GM_BK][GM_BM + 4];
    __shared__ float Bs[GM_BK][GM_BN];

    const int bm = blockIdx.y * GM_BM;
    const int bn = blockIdx.x * GM_BN;
    const int tid = (int)threadIdx.x;
    const int tm = (tid >> 4) << 2;
    const int tn = (tid & 15) << 2;

    unsigned long long acc2[4][2];
    #pragma unroll
    for (int i = 0; i < 4; i++) { acc2[i][0] = 0ull; acc2[i][1] = 0ull; }

    for (int k0 = 0; k0 < F; k0 += GM_BK) {
        #pragma unroll
        for (int i = 0; i < 2; i++) {
            int idx = tid + i * 256;
            int r = idx >> 3;
            int c = (idx & 7) << 2;
            int m = bm + r;
            int t = m >> 8;
            int b = m & 255;
            float4 v = *(const float4*)&x[((size_t)b * T + t) * F + k0 + c];
            As[c + 0][r] = v.x;
            As[c + 1][r] = v.y;
            As[c + 2][r] = v.z;
            As[c + 3][r] = v.w;
        }
        #pragma unroll
        for (int i = 0; i < 2; i++) {
            int idx = tid + i * 256;
            int r = idx >> 4;
            int c = (idx & 15) << 2;
            *(float4*)&Bs[r][c] = *(const float4*)&w[(size_t)(k0 + r) * H3 + bn + c];
        }
        __syncthreads();

        #pragma unroll
        for (int k = 0; k < GM_BK; k++) {
            unsigned long long a0 = dup2(As[k][tm + 0]);
            unsigned long long a1 = dup2(As[k][tm + 1]);
            unsigned long long a2 = dup2(As[k][tm + 2]);
            unsigned long long a3 = dup2(As[k][tm + 3]);
            const unsigned long long* bsk = (const unsigned long long*)&Bs[k][tn];
            unsigned long long b01 = bsk[0];
            unsigned long long b23 = bsk[1];
            ffma2(acc2[0][0], a0, b01); ffma2(acc2[0][1], a0, b23);
            ffma2(acc2[1][0], a1, b01); ffma2(acc2[1][1], a1, b23);
            ffma2(acc2[2][0], a2, b01); ffma2(acc2[2][1], a2, b23);
            ffma2(acc2[3][0], a3, b01); ffma2(acc2[3][1], a3, b23);
        }
        __syncthreads();
    }

    float4 bz4 = *(const float4*)&bias[bn + tn];
    #pragma unroll
    for (int i = 0; i < 4; i++) {
        float2 lo = unpk(acc2[i][0]);
        float2 hi = unpk(acc2[i][1]);
        float4 o;
        o.x = lo.x + bz4.x;
        o.y = lo.y + bz4.y;
        o.z = hi.x + bz4.z;
        o.w = hi.y + bz4.w;
        *(float4*)&g_mx[(size_t)(bm + tm + i) * H3 + bn + tn] = o;
    }
}

// ---------------------------------------------------------------------------
// Kernel 2: persistent GRU recurrence — tf32 tensor-core version.
// Grid (8 j-tiles, 16 b-groups) = 128 blocks, 512 threads, 1 block/SM.
// Block owns a (16 batch x 32 hidden) tile for all 512 steps.
// Weights: 12 mma warps each hold their (256k x 8col) B slice as tf32 in
// 64 REGISTERS (loaded once) -> zero weight smem traffic per step.
// Per step: fused poll+stage of h(t-1) (cvt to tf32 at stage time), bar,
// 12 warps do 32x mma.m16n8k8 (mh for 16x96), write mh tile to smem, bar,
// 512 threads gates+output (recurrence carried in full fp32), bar, flag.
// ---------------------------------------------------------------------------
#define BT 16
#define JT 32
#define HSS 260                     // h row stride floats (16B aligned, skew)
#define HS_FLOATS (BT * HSS)
#define PTS 100                     // mh tile row stride
#define PT_FLOATS (BT * PTS)
#define SMEM_BYTES ((HS_FLOATS + PT_FLOATS) * 4)

extern __shared__ float smem_dyn[];

__global__ __launch_bounds__(512, 1)
void gru_persist(const float* __restrict__ mx,
                 const float* __restrict__ wr,
                 const float* __restrict__ rbias,
                 float* __restrict__ out) {
    float* hs = smem_dyn;                          // [16][HSS] tf32-valued h
    float* pt = hs + HS_FLOATS;                    // [16][PTS] mh tile

    const int tid = (int)threadIdx.x;              // 0..511
    const int wid = tid >> 5;                      // 0..15
    const int lane = tid & 31;
    const int jb = (int)blockIdx.x;                // 0..7
    const int ib = (int)blockIdx.y;                // 0..15
    const int b0 = ib * BT;
    const int j0 = jb * JT;

    // mma fragment indices
    const int g8 = lane >> 2;                      // 0..7
    const int tg = lane & 3;                       // 0..3

    // Phase-C mapping: one (b, j) element per thread
    const int bc = tid >> 5;                       // 0..15 (== wid)
    const int jc = tid & 31;                       // 0..31

    // Stager mapping: warp-pair -> peer j-tile (all 16 warps stage)
    const int sp   = wid >> 1;                     // peer 0..7
    const int srow = (wid & 1) * 8 + (lane >> 2);  // row 0..15
    const int sc4  = lane & 3;                     // f4 col 0..3 (then +4)

    // ---- Preload this warp's B (weights) into registers as tf32 ----
    // Warp w (<12): gate = w>>2, cols jj0..jj0+7 of its 32-col j-tile.
    uint32_t bw[64];
    if (wid < 12) {
        const int gate = wid >> 2;
        const int jj0 = (wid & 3) * 8;
        const int col = gate * H + j0 + jj0 + g8;  // global Wr column
        #pragma unroll
        for (int kc = 0; kc < 32; kc++) {
            int k = kc * 8;
            bw[2 * kc + 0] = f2tf(wr[(size_t)(k + tg) * H3 + col]);
            bw[2 * kc + 1] = f2tf(wr[(size_t)(k + tg + 4) * H3 + col]);
        }
    }

    const float bz = rbias[j0 + jc];
    const float br = rbias[H + j0 + jc];
    const float bh = rbias[2 * H + j0 + jc];

    // Zero hs (step 0 h = 0)
    for (int i = tid; i < HS_FLOATS; i += 512) hs[i] = 0.0f;
    __syncthreads();

    float hp = 0.0f;                               // carried own h element

    for (int t = 0; t < T; t++) {
        // ---- prefetch mx gate inputs (independent of flags) ----
        const float* mxr = mx + ((size_t)t * B + (b0 + bc)) * H3 + (j0 + jc);
        float xz = mxr[0];
        float xr = mxr[H];
        float xh = mxr[2 * H];

        if (t > 0) {
            // ---- fused poll + stage h(t-1), rounding to tf32 ----
            if (sp != jb) {
                const unsigned* fp = &g_flags[ib][sp * 32];
                while (ld_acq(fp) < (unsigned)t) { __nanosleep(20); }
            }
            const float* hrow = out + (size_t)(t - 1) * BH
                              + (size_t)(b0 + srow) * H + sp * 32;
            float4 v0 = *(const float4*)&hrow[sc4 * 4];
            float4 v1 = *(const float4*)&hrow[sc4 * 4 + 16];
            uint4 u0, u1;
            u0.x = f2tf(v0.x); u0.y = f2tf(v0.y); u0.z = f2tf(v0.z); u0.w = f2tf(v0.w);
            u1.x = f2tf(v1.x); u1.y = f2tf(v1.y); u1.z = f2tf(v1.z); u1.w = f2tf(v1.w);
            float* hd = hs + srow * HSS + sp * 32;
            *(uint4*)&hd[sc4 * 4] = u0;
            *(uint4*)&hd[sc4 * 4 + 16] = u1;
            __syncthreads();

            // ---- phase A: mh = h @ Wr via tf32 mma (warps 0..11) ----
            if (wid < 12) {
                const int gate = wid >> 2;
                const int jj0 = (wid & 3) * 8;
                float d0 = 0.f, d1 = 0.f, d2 = 0.f, d3 = 0.f;
                const float* h0 = hs + g8 * HSS;
                const float* h1 = hs + (g8 + 8) * HSS;
                #pragma unroll
                for (int kc = 0; kc < 32; kc++) {
                    const int kb = kc * 8;
                    uint32_t a0 = __float_as_uint(h0[kb + tg]);
                    uint32_t a1 = __float_as_uint(h1[kb + tg]);
                    uint32_t a2 = __float_as_uint(h0[kb + tg + 4]);
                    uint32_t a3 = __float_as_uint(h1[kb + tg + 4]);
                    mma_tf32(d0, d1, d2, d3, a0, a1, a2, a3,
                             bw[2 * kc], bw[2 * kc + 1]);
                }
                // store mh fragments: rows g8 / g8+8, cols gate*32+jj0+2tg(+1)
                float* pr0 = pt + g8 * PTS + gate * 32 + jj0 + 2 * tg;
                float* pr1 = pr0 + 8 * PTS;
                *(float2*)pr0 = make_float2(d0, d1);
                *(float2*)pr1 = make_float2(d2, d3);
            }
        }
        __syncthreads();

        // ---- phase C: gates + output (512 threads, 1 element each) ----
        {
            float mz = 0.f, mr = 0.f, mh = 0.f;
            if (t > 0) {
                const float* p = pt + bc * PTS + jc;
                mz = p[0];
                mr = p[32];
                mh = p[64];
            }
            float z = sig_fast(xz + mz + bz);
            float r = sig_fast(xr + mr + br);
            float c = tanh_fast(xh + r * (mh + bh));
            float o = c + z * (hp - c);
            out[(size_t)t * BH + (size_t)(b0 + bc) * H + j0 + jc] = o;
            hp = o;
        }

        // ---- publish: bar orders all STGs before the release store ----
        __syncthreads();
        if (tid == 0) {
            st_rel(&g_flags[ib][jb * 32], (unsigned)(t + 1));
        }
    }
}

// ---------------------------------------------------------------------------
// Launch
// ---------------------------------------------------------------------------
extern "C" void kernel_launch(void* const* d_in, const int* in_sizes, int n_in,
                              void* d_out, int out_size) {
    (void)in_sizes; (void)n_in; (void)out_size;
    const float* x    = (const float*)d_in[0];   // (B, T, F)
    const float* w    = (const float*)d_in[1];   // (F, 3H)
    const float* wr   = (const float*)d_in[2];   // (H, 3H)
    const float* bias = (const float*)d_in[3];   // (2, 3H)
    float* out = (float*)d_out;                  // (T, B, H)

    static int attr_set = 0;
    if (!attr_set) {
        cudaFuncSetAttribute(gru_persist,
                             cudaFuncAttributeMaxDynamicSharedMemorySize,
                             SMEM_BYTES);
        attr_set = 1;
    }

    float* mx;
    cudaGetSymbolAddress((void**)&mx, g_mx);
    void* flags;
    cudaGetSymbolAddress(&flags, g_flags);

    cudaMemsetAsync(flags, 0, sizeof(unsigned) * NBB * NJB * 32, 0);

    dim3 g1(H3 / GM_BN, (T * B) / GM_BM);        // (12, 2048)
    mx_gemm<<<g1, 256>>>(x, w, bias);

    const float* rbias = bias + H3;
    dim3 g2(NJB, NBB);                           // (8, 16) = 128 blocks
    gru_persist<<<g2, 512, SMEM_BYTES>>>(mx, wr, rbias, out);
}

// round 11
// speedup vs baseline: 3.4304x; 1.2141x over previous
#include <cuda_runtime.h>
#include <math.h>
#include <stdint.h>

#define B 256
#define T 512
#define F 128
#define H 256
#define H3 768
#define BH (B * H)

// Flag array for inter-block sync (one 128B line per flag)
#define NJB 8
#define NBB 16
__device__ unsigned g_flags[NBB][NJB * 32];

// ---------------------------------------------------------------------------
// Helpers
// ---------------------------------------------------------------------------
__device__ __forceinline__ float tanh_fast(float x) {
    float y;
    asm("tanh.approx.f32 %0, %1;" : "=f"(y) : "f"(x));
    return y;
}
__device__ __forceinline__ float sig_fast(float x) {
    return fmaf(0.5f, tanh_fast(0.5f * x), 0.5f);
}
__device__ __forceinline__ unsigned ld_acq(const unsigned* p) {
    unsigned v;
    asm volatile("ld.acquire.gpu.global.u32 %0, [%1];" : "=r"(v) : "l"(p));
    return v;
}
__device__ __forceinline__ void st_rel(unsigned* p, unsigned v) {
    asm volatile("st.release.gpu.global.u32 [%0], %1;" :: "l"(p), "r"(v) : "memory");
}
__device__ __forceinline__ uint32_t f2tf(float x) {
    uint32_t r;
    asm("cvt.rna.tf32.f32 %0, %1;" : "=r"(r) : "f"(x));
    return r;
}
__device__ __forceinline__ void mma_tf32(float& d0, float& d1, float& d2, float& d3,
                                         uint32_t a0, uint32_t a1, uint32_t a2, uint32_t a3,
                                         uint32_t b0, uint32_t b1) {
    asm volatile(
        "mma.sync.aligned.m16n8k8.row.col.f32.tf32.tf32.f32 "
        "{%0,%1,%2,%3}, {%4,%5,%6,%7}, {%8,%9}, {%0,%1,%2,%3};"
        : "+f"(d0), "+f"(d1), "+f"(d2), "+f"(d3)
        : "r"(a0), "r"(a1), "r"(a2), "r"(a3), "r"(b0), "r"(b1));
}

// ---------------------------------------------------------------------------
// Persistent fused GRU kernel.
// Grid (8 j-tiles, 16 b-groups) = 128 blocks, 512 threads, 1 block/SM.
// Block owns a (16 batch x 32 hidden) tile for all 512 steps.
//
// Warps 0-11:  recurrence mh = h(t-1) @ Wr. Wr slice held as tf32 in 64
//              REGISTERS per thread (loaded once).
// Warps 12-15: input projection mxt = x_t @ Wk (+bias in phase C). Wk
//              B-fragments pre-packed in SMEM in fragment order (LDS.64).
// All warps:   stage x_t tile (LDG.128, issued before polls) and peer h
//              tiles (fused poll+stage, cvt to tf32 at stage time).
// Phase C:     512 threads, one (b,j) element each; fp32 gates; STG out;
//              flag publish via st.release.
// ---------------------------------------------------------------------------
#define BT 16
#define JT 32
#define HSS 260                     // h row stride (16B aligned, bank skew)
#define XSS 132                     // x row stride
#define PTS 100                     // mh tile row stride
#define MXS 100                     // mx tile row stride

#define HS_OFF 0
#define XS_OFF (HS_OFF + BT * HSS)          // 4160
#define PT_OFF (XS_OFF + BT * XSS)          // 6272
#define MX_OFF (PT_OFF + BT * PTS)          // 7872
#define KB_OFF (MX_OFF + BT * MXS)          // 9472
#define KB_FLOATS (12 * 16 * 32 * 2)        // 12288
#define SMEM_FLOATS (KB_OFF + KB_FLOATS)    // 21760
#define SMEM_BYTES (SMEM_FLOATS * 4)

extern __shared__ float smem_dyn[];

__global__ __launch_bounds__(512, 1)
void gru_persist(const float* __restrict__ x,
                 const float* __restrict__ wk,
                 const float* __restrict__ wr,
                 const float* __restrict__ bias,
                 float* __restrict__ out) {
    float* hs  = smem_dyn + HS_OFF;                // [16][HSS] tf32 h
    float* xs  = smem_dyn + XS_OFF;                // [16][XSS] tf32 x_t
    float* pt  = smem_dyn + PT_OFF;                // [16][PTS] mh
    float* mxs = smem_dyn + MX_OFF;                // [16][MXS] mx_t
    float2* kb = (float2*)(smem_dyn + KB_OFF);     // [12][16][32] packed Wk frags

    const int tid = (int)threadIdx.x;              // 0..511
    const int wid = tid >> 5;                      // 0..15
    const int lane = tid & 31;
    const int jb = (int)blockIdx.x;                // 0..7
    const int ib = (int)blockIdx.y;                // 0..15
    const int b0 = ib * BT;
    const int j0 = jb * JT;

    // mma fragment indices
    const int g8 = lane >> 2;                      // 0..7
    const int tg = lane & 3;                       // 0..3

    // Phase-C mapping: one (b, j) element per thread
    const int bc = tid >> 5;                       // 0..15
    const int jc = tid & 31;                       // 0..31

    // h stager mapping: warp-pair -> peer j-tile
    const int sp   = wid >> 1;                     // peer 0..7
    const int srow = (wid & 1) * 8 + (lane >> 2);  // row 0..15
    const int sc4  = lane & 3;                     // f4 col 0..3 (then +4)

    // x stager mapping: one LDG.128 per thread
    const int xrow = tid >> 5;                     // 0..15
    const int xcol = lane * 4;                     // 0..124

    // ---- Preload recurrent weights into registers (warps 0-11) ----
    uint32_t bw[64];
    if (wid < 12) {
        const int gate = wid >> 2;
        const int jj0 = (wid & 3) * 8;
        const int col = gate * H + j0 + jj0 + g8;
        #pragma unroll
        for (int kc = 0; kc < 32; kc++) {
            int k = kc * 8;
            bw[2 * kc + 0] = f2tf(wr[(size_t)(k + tg) * H3 + col]);
            bw[2 * kc + 1] = f2tf(wr[(size_t)(k + tg + 4) * H3 + col]);
        }
    } else {
        // ---- Pack input-projection weights into smem fragments ----
        const int q = wid - 12;                    // 0..3
        for (int ci = 0; ci < 3; ci++) {
            const int cc = q * 3 + ci;             // col-chunk 0..11
            const int gate = cc >> 2;
            const int jj0 = (cc & 3) * 8;
            const int col = gate * H + j0 + jj0 + g8;
            #pragma unroll
            for (int kc = 0; kc < 16; kc++) {
                int k = kc * 8;
                float2 v;
                v.x = __uint_as_float(f2tf(wk[(size_t)(k + tg) * H3 + col]));
                v.y = __uint_as_float(f2tf(wk[(size_t)(k + tg + 4) * H3 + col]));
                kb[(cc * 16 + kc) * 32 + lane] = v;
            }
        }
    }

    // Biases for phase C (input + recurrent)
    const float bzi = bias[j0 + jc];
    const float bri = bias[H + j0 + jc];
    const float bhi = bias[2 * H + j0 + jc];
    const float bzr = bias[H3 + j0 + jc];
    const float brr = bias[H3 + H + j0 + jc];
    const float bhr = bias[H3 + 2 * H + j0 + jc];

    // Zero hs (step 0 h = 0)
    for (int i = tid; i < BT * HSS; i += 512) hs[i] = 0.0f;
    __syncthreads();

    float hp = 0.0f;                               // carried own h element

    for (int t = 0; t < T; t++) {
        // ---- stage x_t tile (LDG issued before any poll) ----
        {
            float4 v = *(const float4*)&x[((size_t)(b0 + xrow) * T + t) * F + xcol];
            uint4 u;
            u.x = f2tf(v.x); u.y = f2tf(v.y); u.z = f2tf(v.z); u.w = f2tf(v.w);
            *(uint4*)&xs[xrow * XSS + xcol] = u;
        }

        // ---- fused poll + stage h(t-1), rounding to tf32 ----
        if (t > 0) {
            if (sp != jb) {
                const unsigned* fp = &g_flags[ib][sp * 32];
                while (ld_acq(fp) < (unsigned)t) { __nanosleep(20); }
            }
            const float* hrow = out + (size_t)(t - 1) * BH
                              + (size_t)(b0 + srow) * H + sp * 32;
            float4 v0 = *(const float4*)&hrow[sc4 * 4];
            float4 v1 = *(const float4*)&hrow[sc4 * 4 + 16];
            uint4 u0, u1;
            u0.x = f2tf(v0.x); u0.y = f2tf(v0.y); u0.z = f2tf(v0.z); u0.w = f2tf(v0.w);
            u1.x = f2tf(v1.x); u1.y = f2tf(v1.y); u1.z = f2tf(v1.z); u1.w = f2tf(v1.w);
            float* hd = hs + srow * HSS + sp * 32;
            *(uint4*)&hd[sc4 * 4] = u0;
            *(uint4*)&hd[sc4 * 4 + 16] = u1;
        }
        __syncthreads();

        // ---- mma phase ----
        if (wid < 12) {
            // recurrence: mh = h(t-1) @ Wr  (skip at t=0; h=0)
            if (t > 0) {
                const int gate = wid >> 2;
                const int jj0 = (wid & 3) * 8;
                float d0 = 0.f, d1 = 0.f, d2 = 0.f, d3 = 0.f;
                const float* h0 = hs + g8 * HSS;
                const float* h1 = hs + (g8 + 8) * HSS;
                #pragma unroll
                for (int kc = 0; kc < 32; kc++) {
                    const int kb8 = kc * 8;
                    uint32_t a0 = __float_as_uint(h0[kb8 + tg]);
                    uint32_t a1 = __float_as_uint(h1[kb8 + tg]);
                    uint32_t a2 = __float_as_uint(h0[kb8 + tg + 4]);
                    uint32_t a3 = __float_as_uint(h1[kb8 + tg + 4]);
                    mma_tf32(d0, d1, d2, d3, a0, a1, a2, a3,
                             bw[2 * kc], bw[2 * kc + 1]);
                }
                float* pr0 = pt + g8 * PTS + gate * 32 + jj0 + 2 * tg;
                float* pr1 = pr0 + 8 * PTS;
                *(float2*)pr0 = make_float2(d0, d1);
                *(float2*)pr1 = make_float2(d2, d3);
            }
        } else {
            // input projection: mx_t = x_t @ Wk
            const int q = wid - 12;
            const float* x0 = xs + g8 * XSS;
            const float* x1 = xs + (g8 + 8) * XSS;
            #pragma unroll
            for (int ci = 0; ci < 3; ci++) {
                const int cc = q * 3 + ci;
                float d0 = 0.f, d1 = 0.f, d2 = 0.f, d3 = 0.f;
                #pragma unroll
                for (int kc = 0; kc < 16; kc++) {
                    const int kb8 = kc * 8;
                    uint32_t a0 = __float_as_uint(x0[kb8 + tg]);
                    uint32_t a1 = __float_as_uint(x1[kb8 + tg]);
                    uint32_t a2 = __float_as_uint(x0[kb8 + tg + 4]);
                    uint32_t a3 = __float_as_uint(x1[kb8 + tg + 4]);
                    float2 bb = kb[(cc * 16 + kc) * 32 + lane];
                    mma_tf32(d0, d1, d2, d3, a0, a1, a2, a3,
                             __float_as_uint(bb.x), __float_as_uint(bb.y));
                }
                float* mr0 = mxs + g8 * MXS + cc * 8 + 2 * tg;
                float* mr1 = mr0 + 8 * MXS;
                *(float2*)mr0 = make_float2(d0, d1);
                *(float2*)mr1 = make_float2(d2, d3);
            }
        }
        __syncthreads();

        // ---- phase C: gates + output (512 threads, 1 element each) ----
        {
            const float* mrow = mxs + bc * MXS;
            float xz = mrow[jc] + bzi;
            float xr = mrow[32 + jc] + bri;
            float xh = mrow[64 + jc] + bhi;
            float mz = 0.f, mr = 0.f, mh = 0.f;
            if (t > 0) {
                const float* p = pt + bc * PTS + jc;
                mz = p[0];
                mr = p[32];
                mh = p[64];
            }
            float z = sig_fast(xz + mz + bzr);
            float r = sig_fast(xr + mr + brr);
            float c = tanh_fast(xh + r * (mh + bhr));
            float o = c + z * (hp - c);
            out[(size_t)t * BH + (size_t)(b0 + bc) * H + j0 + jc] = o;
            hp = o;
        }

        // ---- publish: bar orders all STGs before the release store ----
        __syncthreads();
        if (tid == 0) {
            st_rel(&g_flags[ib][jb * 32], (unsigned)(t + 1));
        }
    }
}

// ---------------------------------------------------------------------------
// Launch: flag memset + ONE persistent kernel (projection fused in).
// ---------------------------------------------------------------------------
extern "C" void kernel_launch(void* const* d_in, const int* in_sizes, int n_in,
                              void* d_out, int out_size) {
    (void)in_sizes; (void)n_in; (void)out_size;
    const float* x    = (const float*)d_in[0];   // (B, T, F)
    const float* wk   = (const float*)d_in[1];   // (F, 3H)
    const float* wr   = (const float*)d_in[2];   // (H, 3H)
    const float* bias = (const float*)d_in[3];   // (2, 3H)
    float* out = (float*)d_out;                  // (T, B, H)

    static int attr_set = 0;
    if (!attr_set) {
        cudaFuncSetAttribute(gru_persist,
                             cudaFuncAttributeMaxDynamicSharedMemorySize,
                             SMEM_BYTES);
        attr_set = 1;
    }

    void* flags;
    cudaGetSymbolAddress(&flags, g_flags);
    cudaMemsetAsync(flags, 0, sizeof(unsigned) * NBB * NJB * 32, 0);

    dim3 g2(NJB, NBB);                           // (8, 16) = 128 blocks
    gru_persist<<<g2, 512, SMEM_BYTES>>>(x, wk, wr, bias, out);
}

// round 13
// speedup vs baseline: 6.1726x; 1.7994x over previous
#include <cuda_runtime.h>
#include <cuda_fp16.h>
#include <math.h>
#include <stdint.h>

#define B 256
#define T 512
#define F 128
#define H 256
#define H3 768
#define BH (B * H)

// Flag array for inter-block sync (one 128B line per flag)
#define NJB 8
#define NBB 16
__device__ unsigned g_flags[NBB][NJB * 32];

// ---------------------------------------------------------------------------
// Helpers
// ---------------------------------------------------------------------------
__device__ __forceinline__ float tanh_fast(float x) {
    float y;
    asm("tanh.approx.f32 %0, %1;" : "=f"(y) : "f"(x));
    return y;
}
__device__ __forceinline__ float sig_fast(float x) {
    return fmaf(0.5f, tanh_fast(0.5f * x), 0.5f);
}
__device__ __forceinline__ unsigned ld_acq(const unsigned* p) {
    unsigned v;
    asm volatile("ld.acquire.gpu.global.u32 %0, [%1];" : "=r"(v) : "l"(p));
    return v;
}
__device__ __forceinline__ void st_rel(unsigned* p, unsigned v) {
    asm volatile("st.release.gpu.global.u32 [%0], %1;" :: "l"(p), "r"(v) : "memory");
}
__device__ __forceinline__ uint32_t pack_h2(float lo, float hi) {
    half2 h = __floats2half2_rn(lo, hi);
    return *reinterpret_cast<uint32_t*>(&h);
}
__device__ __forceinline__ void mma_f16(float* d,
                                        uint32_t a0, uint32_t a1, uint32_t a2, uint32_t a3,
                                        uint32_t b0, uint32_t b1) {
    asm volatile(
        "mma.sync.aligned.m16n8k16.row.col.f32.f16.f16.f32 "
        "{%0,%1,%2,%3}, {%4,%5,%6,%7}, {%8,%9}, {%0,%1,%2,%3};"
        : "+f"(d[0]), "+f"(d[1]), "+f"(d[2]), "+f"(d[3])
        : "r"(a0), "r"(a1), "r"(a2), "r"(a3), "r"(b0), "r"(b1));
}

// ---------------------------------------------------------------------------
// Persistent fused GRU kernel (fp16 tensor cores, warp-specialized).
// Grid (8 j-tiles, 16 b-groups) = 128 blocks, 512 threads, 1 block/SM.
//
// Warps 0-5:   recurrence mh = h(t-1) @ Wr; 2 n8-chunks each; Wr frags in
//              64 REGS (fp16). Warps 0-2 also stage peer h tiles.
// Warps 6-11:  input projection for step t+1 (pipelined ahead); Wk frags
//              in 32 REGS; x_{t+1} staged by the same warps; mxs dbl-buf.
// Warps 12-15: peer h tile stagers (fused poll + LDG + cvt f16 + STS).
// Phase C:     all 512 threads, one (b,j) element; fp32 gates; STG out;
//              STS own h (fp16) into hs; flag via st.release.
// ---------------------------------------------------------------------------
#define BT 16
#define JT 32
#define HST 264                     // hs row stride in halves (4-bank skew)
#define XST 136                     // xs row stride in halves
#define PTS 100                     // mh tile row stride (f32)
#define MXS 100                     // mx tile row stride (f32)

#define HS_BYTES (BT * HST * 2)            // 8448
#define XS_BYTES (BT * XST * 2)            // 4352
#define PT_BYTES (BT * PTS * 4)            // 6400
#define MX_BYTES (2 * BT * MXS * 4)        // 12800
#define SMEM_BYTES (HS_BYTES + XS_BYTES + PT_BYTES + MX_BYTES)

extern __shared__ char smem_dyn[];

__global__ __launch_bounds__(512, 1)
void gru_persist(const float* __restrict__ x,
                 const float* __restrict__ wk,
                 const float* __restrict__ wr,
                 const float* __restrict__ bias,
                 float* __restrict__ out) {
    half*  hsh = (half*)(smem_dyn);                         // [16][HST]
    half*  xsh = (half*)(smem_dyn + HS_BYTES);              // [16][XST]
    float* pt  = (float*)(smem_dyn + HS_BYTES + XS_BYTES);  // [16][PTS]
    float* mxs = (float*)(smem_dyn + HS_BYTES + XS_BYTES + PT_BYTES); // [2][16][MXS]

    const int tid = (int)threadIdx.x;              // 0..511
    const int wid = tid >> 5;                      // 0..15
    const int lane = tid & 31;
    const int jb = (int)blockIdx.x;                // 0..7
    const int ib = (int)blockIdx.y;                // 0..15
    const int b0 = ib * BT;
    const int j0 = jb * JT;

    // mma fragment indices
    const int g8 = lane >> 2;                      // 0..7
    const int tg = lane & 3;                       // 0..3

    // Phase-C mapping
    const int bc = tid >> 5;                       // 0..15
    const int jc = tid & 31;                       // 0..31

    // Stager mapping: warps 12-15 -> sidx 0-3, warps 0-2 -> sidx 4-6
    const bool is_stager = (wid >= 12) || (wid < 3);
    const int sidx = (wid >= 12) ? (wid - 12) : (wid + 4);
    const int peer = (jb + 1 + sidx) & 7;          // valid when sidx<7

    // ---- Preload weight fragments into registers ----
    uint32_t bw[64];
    if (wid < 6) {
        const int gate = wid >> 1;
        const int cb = (wid & 1) * 16;
        #pragma unroll
        for (int c = 0; c < 2; c++) {
            const int col = gate * H + j0 + cb + c * 8 + g8;
            #pragma unroll
            for (int kc = 0; kc < 16; kc++) {
                const int kb = kc * 16;
                bw[c * 32 + 2 * kc] =
                    pack_h2(wr[(size_t)(kb + 2 * tg) * H3 + col],
                            wr[(size_t)(kb + 2 * tg + 1) * H3 + col]);
                bw[c * 32 + 2 * kc + 1] =
                    pack_h2(wr[(size_t)(kb + 2 * tg + 8) * H3 + col],
                            wr[(size_t)(kb + 2 * tg + 9) * H3 + col]);
            }
        }
    } else if (wid < 12) {
        const int pw = wid - 6;
        const int gate = pw >> 1;
        const int cb = (pw & 1) * 16;
        #pragma unroll
        for (int c = 0; c < 2; c++) {
            const int col = gate * H + j0 + cb + c * 8 + g8;
            #pragma unroll
            for (int kc = 0; kc < 8; kc++) {
                const int kb = kc * 16;
                bw[c * 16 + 2 * kc] =
                    pack_h2(wk[(size_t)(kb + 2 * tg) * H3 + col],
                            wk[(size_t)(kb + 2 * tg + 1) * H3 + col]);
                bw[c * 16 + 2 * kc + 1] =
                    pack_h2(wk[(size_t)(kb + 2 * tg + 8) * H3 + col],
                            wk[(size_t)(kb + 2 * tg + 9) * H3 + col]);
            }
        }
    }

    // Biases for phase C (input + recurrent)
    const float bzi = bias[j0 + jc];
    const float bri = bias[H + j0 + jc];
    const float bhi = bias[2 * H + j0 + jc];
    const float bzr = bias[H3 + j0 + jc];
    const float brr = bias[H3 + H + j0 + jc];
    const float bhr = bias[H3 + 2 * H + j0 + jc];

    // ---- Prologue: proj group computes mx_0 into mxs[0] ----
    if (wid >= 6 && wid < 12) {
        const int pid = tid - 192;                 // 0..191
        #pragma unroll
        for (int i = 0; i < 3; i++) {
            int idx = pid + i * 192;               // x tile: 16 rows x 32 f4
            if (idx < 512) {
                int row = idx >> 5, c4 = idx & 31;
                float4 v = *(const float4*)&x[((size_t)(b0 + row) * T + 0) * F + c4 * 4];
                uint2 u;
                u.x = pack_h2(v.x, v.y);
                u.y = pack_h2(v.z, v.w);
                *(uint2*)&xsh[row * XST + c4 * 4] = u;
            }
        }
        asm volatile("bar.sync 1, 192;" ::: "memory");
        const int pw = wid - 6;
        float d[2][4] = {};
        const half* x0p = xsh + g8 * XST;
        const half* x1p = xsh + (g8 + 8) * XST;
        #pragma unroll
        for (int kc = 0; kc < 8; kc++) {
            const int kb = kc * 16;
            uint32_t a0 = *(const uint32_t*)&x0p[kb + 2 * tg];
            uint32_t a1 = *(const uint32_t*)&x1p[kb + 2 * tg];
            uint32_t a2 = *(const uint32_t*)&x0p[kb + 2 * tg + 8];
            uint32_t a3 = *(const uint32_t*)&x1p[kb + 2 * tg + 8];
            mma_f16(d[0], a0, a1, a2, a3, bw[2 * kc], bw[2 * kc + 1]);
            mma_f16(d[1], a0, a1, a2, a3, bw[16 + 2 * kc], bw[16 + 2 * kc + 1]);
        }
        #pragma unroll
        for (int c = 0; c < 2; c++) {
            float* mr0 = mxs + g8 * MXS + pw * 16 + c * 8 + 2 * tg;
            *(float2*)mr0 = make_float2(d[c][0], d[c][1]);
            *(float2*)(mr0 + 8 * MXS) = make_float2(d[c][2], d[c][3]);
        }
    }
    __syncthreads();

    float hp = 0.0f;                               // carried own h element

    for (int t = 0; t < T; t++) {
        if (wid >= 6 && wid < 12) {
            // ============ PROJ GROUP: mx_{t+1} (pipelined ahead) ============
            if (t + 1 < T) {
                const int pid = tid - 192;
                #pragma unroll
                for (int i = 0; i < 3; i++) {
                    int idx = pid + i * 192;       // 16 rows x 32 f4 chunks
                    if (idx < 512) {
                        int row = idx >> 5, c4 = idx & 31;
                        float4 v = *(const float4*)
                            &x[((size_t)(b0 + row) * T + (t + 1)) * F + c4 * 4];
                        uint2 u;
                        u.x = pack_h2(v.x, v.y);
                        u.y = pack_h2(v.z, v.w);
                        *(uint2*)&xsh[row * XST + c4 * 4] = u;
                    }
                }
                asm volatile("bar.sync 1, 192;" ::: "memory");
                const int pw = wid - 6;
                float d[2][4] = {};
                const half* x0p = xsh + g8 * XST;
                const half* x1p = xsh + (g8 + 8) * XST;
                #pragma unroll
                for (int kc = 0; kc < 8; kc++) {
                    const int kb = kc * 16;
                    uint32_t a0 = *(const uint32_t*)&x0p[kb + 2 * tg];
                    uint32_t a1 = *(const uint32_t*)&x1p[kb + 2 * tg];
                    uint32_t a2 = *(const uint32_t*)&x0p[kb + 2 * tg + 8];
                    uint32_t a3 = *(const uint32_t*)&x1p[kb + 2 * tg + 8];
                    mma_f16(d[0], a0, a1, a2, a3, bw[2 * kc], bw[2 * kc + 1]);
                    mma_f16(d[1], a0, a1, a2, a3, bw[16 + 2 * kc], bw[16 + 2 * kc + 1]);
                }
                float* mxb = mxs + ((t + 1) & 1) * (BT * MXS);
                #pragma unroll
                for (int c = 0; c < 2; c++) {
                    float* mr0 = mxb + g8 * MXS + pw * 16 + c * 8 + 2 * tg;
                    *(float2*)mr0 = make_float2(d[c][0], d[c][1]);
                    *(float2*)(mr0 + 8 * MXS) = make_float2(d[c][2], d[c][3]);
                }
            }
        } else if (is_stager && t > 0) {
            // ============ STAGERS: poll + stage one peer h tile ============
            if (lane == 0) {
                const unsigned* fp = &g_flags[ib][peer * 32];
                while (ld_acq(fp) < (unsigned)t) { __nanosleep(20); }
            }
            __syncwarp();
            const float* hsrc = out + (size_t)(t - 1) * BH;
            #pragma unroll
            for (int i = 0; i < 4; i++) {
                int idx = lane + i * 32;           // peer tile: 16 rows x 8 f4
                int row = idx >> 3, c4 = idx & 7;
                float4 v = *(const float4*)
                    &hsrc[(size_t)(b0 + row) * H + peer * 32 + c4 * 4];
                uint2 u;
                u.x = pack_h2(v.x, v.y);
                u.y = pack_h2(v.z, v.w);
                *(uint2*)&hsh[row * HST + peer * 32 + c4 * 4] = u;
            }
        }
        __syncthreads();   // barA: hs complete (stagers + last step's own STS)

        // ============ REC WARPS: mh = h(t-1) @ Wr ============
        if (wid < 6 && t > 0) {
            float d[2][4] = {};
            const half* h0p = hsh + g8 * HST;
            const half* h1p = hsh + (g8 + 8) * HST;
            #pragma unroll
            for (int kc = 0; kc < 16; kc++) {
                const int kb = kc * 16;
                uint32_t a0 = *(const uint32_t*)&h0p[kb + 2 * tg];
                uint32_t a1 = *(const uint32_t*)&h1p[kb + 2 * tg];
                uint32_t a2 = *(const uint32_t*)&h0p[kb + 2 * tg + 8];
                uint32_t a3 = *(const uint32_t*)&h1p[kb + 2 * tg + 8];
                mma_f16(d[0], a0, a1, a2, a3, bw[2 * kc], bw[2 * kc + 1]);
                mma_f16(d[1], a0, a1, a2, a3, bw[32 + 2 * kc], bw[32 + 2 * kc + 1]);
            }
            #pragma unroll
            for (int c = 0; c < 2; c++) {
                float* pr0 = pt + g8 * PTS + wid * 16 + c * 8 + 2 * tg;
                *(float2*)pr0 = make_float2(d[c][0], d[c][1]);
                *(float2*)(pr0 + 8 * PTS) = make_float2(d[c][2], d[c][3]);
            }
        }
        __syncthreads();   // barB: pt ready

        // ============ PHASE C: gates + output (all 512 threads) ============
        {
            const float* mrow = mxs + (t & 1) * (BT * MXS) + bc * MXS;
            float xz = mrow[jc] + bzi;
            float xr = mrow[32 + jc] + bri;
            float xh = mrow[64 + jc] + bhi;
            float mz = 0.f, mr = 0.f, mh = 0.f;
            if (t > 0) {
                const float* p = pt + bc * PTS + jc;
                mz = p[0];
                mr = p[32];
                mh = p[64];
            }
            float z = sig_fast(xz + mz + bzr);
            float r = sig_fast(xr + mr + brr);
            float c = tanh_fast(xh + r * (mh + bhr));
            float o = c + z * (hp - c);
            out[(size_t)t * BH + (size_t)(b0 + bc) * H + j0 + jc] = o;
            hsh[bc * HST + j0 + jc] = __float2half_rn(o);  // own tile, no L2
            hp = o;
        }
        __syncthreads();   // barC: all STGs/STS ordered before release
        if (tid == 0) {
            st_rel(&g_flags[ib][jb * 32], (unsigned)(t + 1));
        }
    }
}

// ---------------------------------------------------------------------------
// Launch
// ---------------------------------------------------------------------------
extern "C" void kernel_launch(void* const* d_in, const int* in_sizes, int n_in,
                              void* d_out, int out_size) {
    (void)in_sizes; (void)n_in; (void)out_size;
    const float* x    = (const float*)d_in[0];   // (B, T, F)
    const float* wk   = (const float*)d_in[1];   // (F, 3H)
    const float* wr   = (const float*)d_in[2];   // (H, 3H)
    const float* bias = (const float*)d_in[3];   // (2, 3H)
    float* out = (float*)d_out;                  // (T, B, H)

    static int attr_set = 0;
    if (!attr_set) {
        cudaFuncSetAttribute(gru_persist,
                             cudaFuncAttributeMaxDynamicSharedMemorySize,
                             SMEM_BYTES);
        attr_set = 1;
    }

    void* flags;
    cudaGetSymbolAddress(&flags, g_flags);
    cudaMemsetAsync(flags, 0, sizeof(unsigned) * NBB * NJB * 32, 0);

    dim3 g2(NJB, NBB);                           // (8, 16) = 128 blocks
    gru_persist<<<g2, 512, SMEM_BYTES>>>(x, wk, wr, bias, out);
}